// round 1
// baseline (speedup 1.0000x reference)
#include <cuda_runtime.h>
#include <math.h>

// Problem dims
#define BATCH 16
#define SEQ   1024
#define EMB   256
#define NTOK  16384   // BATCH*SEQ
#define NHEAD 8
#define DHEAD 32

// Output layout: logits[16] | probas[16] | final_vector[16*1024*256] | ssm[16*256]
#define OFF_PROBAS 16
#define OFF_FINAL  32
#define OFF_SSM    (32 + NTOK*EMB)

// -------- scratch (device globals; no allocations allowed) --------
__device__ float g_x[NTOK * EMB];
__device__ float g_ln[NTOK * EMB];
__device__ float g_qkv[NTOK * 3 * EMB];
__device__ float g_ctx[NTOK * EMB];
__device__ float g_ffn[NTOK * 4 * EMB];
__device__ float g_xproj[NTOK * EMB];
__device__ float g_hlast[BATCH * EMB];

// ============================================================================
// Generic tiled fp32 GEMM: C[M,N] = A[M,K] @ W[N,K]^T (+bias +res +pos, act)
// BM=BN=128, BK=16, 256 threads, 8x8 microtile per thread.
// All M,N divisible by 128; K divisible by 16. W row stride = ldw.
// act: 0 = none, 1 = exact GELU
// ============================================================================
__global__ __launch_bounds__(256, 2)
void gemm_kernel(const float* __restrict__ A, const float* __restrict__ W, int ldw,
                 const float* __restrict__ bias, const float* __restrict__ res,
                 const float* __restrict__ pos, float* __restrict__ C,
                 int M, int N, int K, int act)
{
    __shared__ float As[16][128];
    __shared__ float Ws[16][128];

    int tid = threadIdx.x;
    int m0 = blockIdx.y * 128;
    int n0 = blockIdx.x * 128;
    int ty = tid >> 4;      // 0..15 (M dir)
    int tx = tid & 15;      // 0..15 (N dir)

    float acc[8][8];
    #pragma unroll
    for (int i = 0; i < 8; i++)
        #pragma unroll
        for (int j = 0; j < 8; j++) acc[i][j] = 0.f;

    for (int kt = 0; kt < K; kt += 16) {
        #pragma unroll
        for (int i = 0; i < 2; i++) {
            int idx = tid + i * 256;           // 0..511 float4 slots
            int row = idx >> 2;                // 0..127
            int c4  = (idx & 3) << 2;          // 0,4,8,12
            float4 av = *(const float4*)(A + (size_t)(m0 + row) * K + kt + c4);
            As[c4 + 0][row] = av.x; As[c4 + 1][row] = av.y;
            As[c4 + 2][row] = av.z; As[c4 + 3][row] = av.w;
            float4 wv = *(const float4*)(W + (size_t)(n0 + row) * ldw + kt + c4);
            Ws[c4 + 0][row] = wv.x; Ws[c4 + 1][row] = wv.y;
            Ws[c4 + 2][row] = wv.z; Ws[c4 + 3][row] = wv.w;
        }
        __syncthreads();

        #pragma unroll
        for (int kk = 0; kk < 16; kk++) {
            float a[8], w[8];
            *(float4*)&a[0] = *(const float4*)&As[kk][ty * 8];
            *(float4*)&a[4] = *(const float4*)&As[kk][ty * 8 + 4];
            *(float4*)&w[0] = *(const float4*)&Ws[kk][tx * 8];
            *(float4*)&w[4] = *(const float4*)&Ws[kk][tx * 8 + 4];
            #pragma unroll
            for (int i = 0; i < 8; i++)
                #pragma unroll
                for (int j = 0; j < 8; j++)
                    acc[i][j] += a[i] * w[j];
        }
        __syncthreads();
    }

    #pragma unroll
    for (int i = 0; i < 8; i++) {
        int m = m0 + ty * 8 + i;
        #pragma unroll
        for (int j = 0; j < 8; j++) {
            int n = n0 + tx * 8 + j;
            float v = acc[i][j];
            if (bias) v += bias[n];
            if (res)  v += res[(size_t)m * N + n];
            if (pos)  v += pos[(size_t)(m & (SEQ - 1)) * N + n];
            if (act == 1) v = 0.5f * v * (1.0f + erff(v * 0.7071067811865475f));
            C[(size_t)m * N + n] = v;
        }
    }
}

// ============================================================================
// LayerNorm over E=256. One warp per row. y = (x-mu)*rsqrt(var+eps)*g + b
// ============================================================================
__global__ __launch_bounds__(256)
void ln_kernel(const float* __restrict__ x, const float* __restrict__ g,
               const float* __restrict__ bt, float* __restrict__ y)
{
    int w = threadIdx.x >> 5, lane = threadIdx.x & 31;
    int row = blockIdx.x * 8 + w;
    const float* xr = x + (size_t)row * EMB;
    float4 v1 = *(const float4*)(xr + lane * 4);
    float4 v2 = *(const float4*)(xr + 128 + lane * 4);

    float s  = v1.x + v1.y + v1.z + v1.w + v2.x + v2.y + v2.z + v2.w;
    float ss = v1.x*v1.x + v1.y*v1.y + v1.z*v1.z + v1.w*v1.w
             + v2.x*v2.x + v2.y*v2.y + v2.z*v2.z + v2.w*v2.w;
    #pragma unroll
    for (int o = 16; o; o >>= 1) {
        s  += __shfl_xor_sync(0xFFFFFFFFu, s,  o);
        ss += __shfl_xor_sync(0xFFFFFFFFu, ss, o);
    }
    float mu  = s * (1.0f / EMB);
    float var = ss * (1.0f / EMB) - mu * mu;
    float rs  = rsqrtf(var + 1e-5f);

    float* yr = y + (size_t)row * EMB;
    int c = lane * 4;
    float4 o1, o2;
    o1.x = (v1.x - mu) * rs * g[c + 0] + bt[c + 0];
    o1.y = (v1.y - mu) * rs * g[c + 1] + bt[c + 1];
    o1.z = (v1.z - mu) * rs * g[c + 2] + bt[c + 2];
    o1.w = (v1.w - mu) * rs * g[c + 3] + bt[c + 3];
    o2.x = (v2.x - mu) * rs * g[c + 128] + bt[c + 128];
    o2.y = (v2.y - mu) * rs * g[c + 129] + bt[c + 129];
    o2.z = (v2.z - mu) * rs * g[c + 130] + bt[c + 130];
    o2.w = (v2.w - mu) * rs * g[c + 131] + bt[c + 131];
    *(float4*)(yr + c) = o1;
    *(float4*)(yr + 128 + c) = o2;
}

// ============================================================================
// Flash attention, fp32, online softmax. DH=32 in registers.
// grid (SEQ/256, NHEAD, BATCH), 128 threads, 2 queries per thread.
// qkv layout: [tok, 768]; q at h*32, k at 256+h*32, v at 512+h*32
// ============================================================================
__global__ __launch_bounds__(128)
void attn_kernel(const float* __restrict__ qkv, float* __restrict__ ctx)
{
    __shared__ float Ks[64][32];
    __shared__ float Vs[64][32];

    int b = blockIdx.z, h = blockIdx.y;
    int tid = threadIdx.x;
    const float scale = 0.17677669529663687f;   // 1/sqrt(32)

    int qidx0 = blockIdx.x * 256 + tid;
    int qidx1 = qidx0 + 128;

    const float* qb = qkv + (size_t)b * SEQ * 768 + h * DHEAD;

    float q[2][32], acc[2][32];
    float mm[2] = { -1e30f, -1e30f };
    float ll[2] = { 0.f, 0.f };
    #pragma unroll
    for (int d4 = 0; d4 < 8; d4++) {
        float4 v0 = *(const float4*)(qb + (size_t)qidx0 * 768 + d4 * 4);
        float4 v1 = *(const float4*)(qb + (size_t)qidx1 * 768 + d4 * 4);
        q[0][d4*4+0] = v0.x; q[0][d4*4+1] = v0.y; q[0][d4*4+2] = v0.z; q[0][d4*4+3] = v0.w;
        q[1][d4*4+0] = v1.x; q[1][d4*4+1] = v1.y; q[1][d4*4+2] = v1.z; q[1][d4*4+3] = v1.w;
    }
    #pragma unroll
    for (int j = 0; j < 2; j++)
        #pragma unroll
        for (int d = 0; d < 32; d++) acc[j][d] = 0.f;

    for (int kc = 0; kc < SEQ; kc += 64) {
        #pragma unroll
        for (int i = 0; i < 4; i++) {
            int fidx = tid + i * 128;      // 0..511
            int key = fidx >> 3;
            int c = (fidx & 7) << 2;
            const float* src = qkv + (size_t)(b * SEQ + kc + key) * 768 + h * DHEAD;
            *(float4*)&Ks[key][c] = *(const float4*)(src + 256 + c);
            *(float4*)&Vs[key][c] = *(const float4*)(src + 512 + c);
        }
        __syncthreads();

        for (int kk = 0; kk < 64; kk++) {
            float s0 = 0.f, s1 = 0.f;
            #pragma unroll
            for (int d4 = 0; d4 < 8; d4++) {
                float4 kv = *(const float4*)&Ks[kk][d4 * 4];
                s0 += q[0][d4*4+0]*kv.x + q[0][d4*4+1]*kv.y + q[0][d4*4+2]*kv.z + q[0][d4*4+3]*kv.w;
                s1 += q[1][d4*4+0]*kv.x + q[1][d4*4+1]*kv.y + q[1][d4*4+2]*kv.z + q[1][d4*4+3]*kv.w;
            }
            s0 *= scale; s1 *= scale;

            float p0, p1;
            if (s0 > mm[0]) {
                float al = __expf(mm[0] - s0);
                ll[0] *= al;
                #pragma unroll
                for (int d = 0; d < 32; d++) acc[0][d] *= al;
                mm[0] = s0; p0 = 1.f;
            } else p0 = __expf(s0 - mm[0]);
            ll[0] += p0;
            if (s1 > mm[1]) {
                float al = __expf(mm[1] - s1);
                ll[1] *= al;
                #pragma unroll
                for (int d = 0; d < 32; d++) acc[1][d] *= al;
                mm[1] = s1; p1 = 1.f;
            } else p1 = __expf(s1 - mm[1]);
            ll[1] += p1;

            #pragma unroll
            for (int d4 = 0; d4 < 8; d4++) {
                float4 vv = *(const float4*)&Vs[kk][d4 * 4];
                acc[0][d4*4+0] += p0 * vv.x; acc[0][d4*4+1] += p0 * vv.y;
                acc[0][d4*4+2] += p0 * vv.z; acc[0][d4*4+3] += p0 * vv.w;
                acc[1][d4*4+0] += p1 * vv.x; acc[1][d4*4+1] += p1 * vv.y;
                acc[1][d4*4+2] += p1 * vv.z; acc[1][d4*4+3] += p1 * vv.w;
            }
        }
        __syncthreads();
    }

    float inv0 = 1.f / ll[0], inv1 = 1.f / ll[1];
    float* dst0 = ctx + (size_t)(b * SEQ + qidx0) * EMB + h * DHEAD;
    float* dst1 = ctx + (size_t)(b * SEQ + qidx1) * EMB + h * DHEAD;
    #pragma unroll
    for (int d4 = 0; d4 < 8; d4++) {
        float4 o0, o1;
        o0.x = acc[0][d4*4+0]*inv0; o0.y = acc[0][d4*4+1]*inv0;
        o0.z = acc[0][d4*4+2]*inv0; o0.w = acc[0][d4*4+3]*inv0;
        o1.x = acc[1][d4*4+0]*inv1; o1.y = acc[1][d4*4+1]*inv1;
        o1.z = acc[1][d4*4+2]*inv1; o1.w = acc[1][d4*4+3]*inv1;
        *(float4*)(dst0 + d4*4) = o0;
        *(float4*)(dst1 + d4*4) = o1;
    }
}

// ============================================================================
// Sequential RNN scan. One CTA per batch element (independent recurrences).
// h = relu_mask(tanh(xproj[t] + h @ Wh^T)), Wh = i2h_W[:, 256:512]
// ============================================================================
__global__ __launch_bounds__(256)
void scan_kernel(const float* __restrict__ xproj, const float* __restrict__ i2h_W,
                 const float* __restrict__ h0, float* __restrict__ hlast)
{
    __shared__ float4 hs[64];   // h[256]
    int b = blockIdx.x, e = threadIdx.x;
    ((float*)hs)[e] = h0[b * EMB + e];
    const float4* Wh = (const float4*)(i2h_W + (size_t)e * 512 + 256);
    const float* xp = xproj + (size_t)b * SEQ * EMB + e;
    __syncthreads();

    for (int t = 0; t < SEQ; t++) {
        float acc = xp[t * EMB];
        #pragma unroll 16
        for (int k = 0; k < 64; k++) {
            float4 w = __ldg(&Wh[k]);
            float4 hv = hs[k];
            acc += w.x*hv.x + w.y*hv.y + w.z*hv.z + w.w*hv.w;
        }
        float th = tanhf(acc);
        th = th > 0.f ? th : 0.f;
        __syncthreads();
        ((float*)hs)[e] = th;
        __syncthreads();
    }
    hlast[b * EMB + e] = ((float*)hs)[e];
}

// ============================================================================
// Final head: ssm = h_last @ h2o^T + b;  logits = ssm @ cls^T + cls_b; sigmoid
// ============================================================================
__global__ __launch_bounds__(256)
void final_kernel(const float* __restrict__ hlast, const float* __restrict__ h2o_W,
                  const float* __restrict__ h2o_b, const float* __restrict__ cls_W,
                  const float* __restrict__ cls_b, float* __restrict__ out)
{
    __shared__ float hs[EMB];
    __shared__ float red[EMB];
    int b = blockIdx.x, e = threadIdx.x;
    hs[e] = hlast[b * EMB + e];
    __syncthreads();

    float acc = h2o_b[e];
    const float4* wr = (const float4*)(h2o_W + (size_t)e * EMB);
    const float4* h4 = (const float4*)hs;
    #pragma unroll 16
    for (int k = 0; k < 64; k++) {
        float4 w = __ldg(&wr[k]);
        float4 hv = h4[k];
        acc += w.x*hv.x + w.y*hv.y + w.z*hv.z + w.w*hv.w;
    }
    out[OFF_SSM + b * EMB + e] = acc;
    red[e] = acc * cls_W[e];
    __syncthreads();
    #pragma unroll
    for (int o = 128; o; o >>= 1) {
        if (e < o) red[e] += red[e + o];
        __syncthreads();
    }
    if (e == 0) {
        float logit = red[0] + cls_b[0];
        out[b] = logit;
        out[OFF_PROBAS + b] = 1.f / (1.f + expf(-logit));
    }
}

// ============================================================================
// float4 copy: final_vector -> output region
// ============================================================================
__global__ __launch_bounds__(256)
void copy_kernel(const float* __restrict__ src, float* __restrict__ dst, int n4)
{
    int i = blockIdx.x * blockDim.x + threadIdx.x;
    if (i < n4) ((float4*)dst)[i] = ((const float4*)src)[i];
}

// ============================================================================
extern "C" void kernel_launch(void* const* d_in, const int* in_sizes, int n_in,
                              void* d_out, int out_size)
{
    const float* text_emb = (const float*)d_in[0];
    // d_in[1..3]: image_embeddings, text_mask, image_mask — unused (visn discarded)
    const float* pos     = (const float*)d_in[4];
    const float* text_W  = (const float*)d_in[5];
    const float* text_b  = (const float*)d_in[6];
    const float* ln1_g   = (const float*)d_in[9];
    const float* ln1_b   = (const float*)d_in[10];
    const float* qkv_W   = (const float*)d_in[11];
    const float* qkv_b   = (const float*)d_in[12];
    const float* out_W   = (const float*)d_in[13];
    const float* out_b   = (const float*)d_in[14];
    const float* ln2_g   = (const float*)d_in[15];
    const float* ln2_b   = (const float*)d_in[16];
    const float* ffn_W1  = (const float*)d_in[17];
    const float* ffn_b1  = (const float*)d_in[18];
    const float* ffn_W2  = (const float*)d_in[19];
    const float* ffn_b2  = (const float*)d_in[20];
    const float* cls_W   = (const float*)d_in[21];
    const float* cls_b   = (const float*)d_in[22];
    const float* i2h_W   = (const float*)d_in[23];
    const float* i2h_b   = (const float*)d_in[24];
    const float* h2o_W   = (const float*)d_in[25];
    const float* h2o_b   = (const float*)d_in[26];
    const float* h0      = (const float*)d_in[27];
    float* out = (float*)d_out;

    float *x, *ln, *qkv, *ctx, *ffn, *xproj, *hlast;
    cudaGetSymbolAddress((void**)&x,     g_x);
    cudaGetSymbolAddress((void**)&ln,    g_ln);
    cudaGetSymbolAddress((void**)&qkv,   g_qkv);
    cudaGetSymbolAddress((void**)&ctx,   g_ctx);
    cudaGetSymbolAddress((void**)&ffn,   g_ffn);
    cudaGetSymbolAddress((void**)&xproj, g_xproj);
    cudaGetSymbolAddress((void**)&hlast, g_hlast);

    // 1) lang = text_emb @ text_W^T + text_b + pos_emb
    gemm_kernel<<<dim3(2, 128), 256>>>(text_emb, text_W, 768, text_b, nullptr, pos,
                                       x, NTOK, EMB, 768, 0);

    // 2) two encoder layers (pre-LN)
    for (int l = 0; l < 2; l++) {
        ln_kernel<<<NTOK / 8, 256>>>(x, ln1_g + l * EMB, ln1_b + l * EMB, ln);
        gemm_kernel<<<dim3(6, 128), 256>>>(ln, qkv_W + (size_t)l * 768 * EMB, EMB,
                                           qkv_b + l * 768, nullptr, nullptr,
                                           qkv, NTOK, 768, EMB, 0);
        attn_kernel<<<dim3(SEQ / 256, NHEAD, BATCH), 128>>>(qkv, ctx);
        gemm_kernel<<<dim3(2, 128), 256>>>(ctx, out_W + (size_t)l * EMB * EMB, EMB,
                                           out_b + l * EMB, x, nullptr,
                                           x, NTOK, EMB, EMB, 0);
        ln_kernel<<<NTOK / 8, 256>>>(x, ln2_g + l * EMB, ln2_b + l * EMB, ln);
        gemm_kernel<<<dim3(8, 128), 256>>>(ln, ffn_W1 + (size_t)l * 1024 * EMB, EMB,
                                           ffn_b1 + l * 1024, nullptr, nullptr,
                                           ffn, NTOK, 1024, EMB, 1);
        gemm_kernel<<<dim3(2, 128), 256>>>(ffn, ffn_W2 + (size_t)l * EMB * 1024, 1024,
                                           ffn_b2 + l * EMB, x, nullptr,
                                           x, NTOK, EMB, 1024, 0);
    }

    // 3) final_vector -> output
    copy_kernel<<<(NTOK * EMB / 4 + 255) / 256, 256>>>(x, out + OFF_FINAL, NTOK * EMB / 4);

    // 4) RNN input projection: xproj = x @ Wx^T + i2h_b  (Wx = i2h_W[:, :256], row stride 512)
    gemm_kernel<<<dim3(2, 128), 256>>>(x, i2h_W, 512, i2h_b, nullptr, nullptr,
                                       xproj, NTOK, EMB, EMB, 0);

    // 5) sequential scan (per-batch independent)
    scan_kernel<<<BATCH, 256>>>(xproj, i2h_W, h0, hlast);

    // 6) head: ssm, logits, probas
    final_kernel<<<BATCH, 256>>>(hlast, h2o_W, h2o_b, cls_W, cls_b, out);
}

// round 7
// speedup vs baseline: 1.0288x; 1.0288x over previous
#include <cuda_runtime.h>
#include <cstdint>
#include <math.h>

// Problem dims
#define BATCH 16
#define SEQ   1024
#define EMB   256
#define NTOK  16384   // BATCH*SEQ
#define NHEAD 8
#define DHEAD 32

// Output layout: logits[16] | probas[16] | final_vector[16*1024*256] | ssm[16*256]
#define OFF_PROBAS 16
#define OFF_FINAL  32
#define OFF_SSM    (32 + NTOK*EMB)

// -------- scratch (device globals; no allocations allowed) --------
__device__ float g_x[NTOK * EMB];
__device__ float g_ln[NTOK * EMB];
__device__ float g_qkv[NTOK * 3 * EMB];
__device__ float g_ctx[NTOK * EMB];
__device__ float g_ffn[NTOK * 4 * EMB];
__device__ float g_xproj[NTOK * EMB];
__device__ float g_hlast[BATCH * EMB];

// ================= PTX helpers =================
__device__ __forceinline__ uint32_t smem_u32(const void* p) {
    uint32_t a;
    asm("{ .reg .u64 t; cvta.to.shared.u64 t, %1; cvt.u32.u64 %0, t; }" : "=r"(a) : "l"(p));
    return a;
}
#define CP_ASYNC16(dst, src) \
    asm volatile("cp.async.cg.shared.global [%0], [%1], 16;" :: "r"(dst), "l"(src) : "memory")
#define CP_COMMIT() asm volatile("cp.async.commit_group;" ::: "memory")
#define CP_WAIT1()  asm volatile("cp.async.wait_group 1;" ::: "memory")
#define CP_WAIT0()  asm volatile("cp.async.wait_group 0;" ::: "memory")

// 3xTF32 split: v = hi + lo with hi,lo tf32-representable.
// sub.rn.f32 via asm so the residual can't be contracted away.
__device__ __forceinline__ void split_tf32(float v, uint32_t& hi, uint32_t& lo) {
    asm("cvt.rna.tf32.f32 %0, %1;" : "=r"(hi) : "f"(v));
    float r;
    asm("sub.rn.f32 %0, %1, %2;" : "=f"(r) : "f"(v), "f"(__uint_as_float(hi)));
    asm("cvt.rna.tf32.f32 %0, %1;" : "=r"(lo) : "f"(r));
}

__device__ __forceinline__ void mma_tf32(float* d,
                                         uint32_t a0, uint32_t a1, uint32_t a2, uint32_t a3,
                                         uint32_t b0, uint32_t b1) {
    asm volatile(
        "mma.sync.aligned.m16n8k8.row.col.f32.tf32.tf32.f32 "
        "{%0,%1,%2,%3}, {%4,%5,%6,%7}, {%8,%9}, {%0,%1,%2,%3};"
        : "+f"(d[0]), "+f"(d[1]), "+f"(d[2]), "+f"(d[3])
        : "r"(a0), "r"(a1), "r"(a2), "r"(a3), "r"(b0), "r"(b1));
}

// ============================================================================
// 3xTF32 mma.sync GEMM: C[M,N] = A[M,K] @ W[N,K]^T (+bias +res +pos, act)
// BM=BN=128, BK=32, 256 threads (4x2 warps, 32x64 warp tile).
// Smem rows padded to 36 floats. Near-fp32 accuracy via
// a_lo*b_hi + a_hi*b_lo + a_hi*b_hi. act: 0 none, 1 exact GELU.
// ============================================================================
#define PAD 36
#define STG_FLOATS (128 * PAD)            // per-operand stage: 4608 floats
#define STAGE_BYTES (2 * STG_FLOATS * 4)  // A+B: 36864 bytes

__global__ __launch_bounds__(256)
void gemm_tc(const float* __restrict__ A, const float* __restrict__ W, int ldw,
             const float* __restrict__ bias, const float* __restrict__ res,
             const float* __restrict__ pos, float* __restrict__ C,
             int M, int N, int K, int act)
{
    extern __shared__ float smem[];   // [2 stages][A 128*36 | B 128*36]

    int tid = threadIdx.x;
    int wid = tid >> 5, lane = tid & 31;
    int wm = wid & 3;          // 0..3 -> 32 rows each
    int wn = wid >> 2;         // 0..1 -> 64 cols each
    int m0 = blockIdx.y * 128;
    int n0 = blockIdx.x * 128;

    uint32_t sbase = smem_u32(smem);

    // G->S load mapping: each thread loads 4 float4 of A and 4 of B per stage.
    int lrow = tid >> 1;               // 0..127
    int lc0  = (tid & 1) * 4;          // starting float4 chunk (0 or 4)
    const float* gA = A + (size_t)(m0 + lrow) * K;
    const float* gB = W + (size_t)(n0 + lrow) * ldw;
    uint32_t dstA = sbase + (uint32_t)(lrow * PAD * 4) + (uint32_t)(lc0 * 16);
    uint32_t dstB = dstA + (uint32_t)(STG_FLOATS * 4);

    float acc[2][8][4];
    #pragma unroll
    for (int i = 0; i < 2; i++)
        #pragma unroll
        for (int j = 0; j < 8; j++)
            #pragma unroll
            for (int r = 0; r < 4; r++) acc[i][j][r] = 0.f;

    int CCH = K >> 5;

    // prefetch chunk 0 -> stage 0
    #pragma unroll
    for (int j = 0; j < 4; j++) {
        CP_ASYNC16(dstA + j * 16u, gA + (lc0 + j) * 4);
        CP_ASYNC16(dstB + j * 16u, gB + (lc0 + j) * 4);
    }
    CP_COMMIT();

    // fragment base offsets (floats)
    int qr = lane >> 2;        // 0..7 (groupID)
    int qc = lane & 3;         // 0..3 (threadID_in_group)
    int aoff = (wm * 32 + qr) * PAD + qc;              // + mi*16*PAD + ks*8
    int boff = (wn * 64 + qr) * PAD + qc;              // + ni*8*PAD  + ks*8

    for (int c = 0; c < CCH; c++) {
        int st = c & 1;
        if (c + 1 < CCH) {
            int s2 = st ^ 1;
            uint32_t dA = dstA + (uint32_t)(s2 * STAGE_BYTES);
            uint32_t dB = dstB + (uint32_t)(s2 * STAGE_BYTES);
            const float* pA = gA + ((c + 1) << 5);
            const float* pB = gB + ((c + 1) << 5);
            #pragma unroll
            for (int j = 0; j < 4; j++) {
                CP_ASYNC16(dA + j * 16u, pA + (lc0 + j) * 4);
                CP_ASYNC16(dB + j * 16u, pB + (lc0 + j) * 4);
            }
            CP_COMMIT();
            CP_WAIT1();
        } else {
            CP_WAIT0();
        }
        __syncthreads();

        const float* As = smem + st * (2 * STG_FLOATS);
        const float* Bs = As + STG_FLOATS;

        #pragma unroll
        for (int ks = 0; ks < 4; ks++) {
            int kb = ks * 8;
            uint32_t ah[2][4], al[2][4];
            #pragma unroll
            for (int mi = 0; mi < 2; mi++) {
                const float* ap = As + aoff + mi * 16 * PAD + kb;
                split_tf32(ap[0],           ah[mi][0], al[mi][0]);
                split_tf32(ap[8 * PAD],     ah[mi][1], al[mi][1]);
                split_tf32(ap[4],           ah[mi][2], al[mi][2]);
                split_tf32(ap[8 * PAD + 4], ah[mi][3], al[mi][3]);
            }
            #pragma unroll
            for (int ni = 0; ni < 8; ni++) {
                const float* bp = Bs + boff + ni * 8 * PAD + kb;
                uint32_t b0h, b0l, b1h, b1l;
                split_tf32(bp[0], b0h, b0l);
                split_tf32(bp[4], b1h, b1l);
                #pragma unroll
                for (int mi = 0; mi < 2; mi++) {
                    mma_tf32(acc[mi][ni], al[mi][0], al[mi][1], al[mi][2], al[mi][3], b0h, b1h);
                    mma_tf32(acc[mi][ni], ah[mi][0], ah[mi][1], ah[mi][2], ah[mi][3], b0l, b1l);
                    mma_tf32(acc[mi][ni], ah[mi][0], ah[mi][1], ah[mi][2], ah[mi][3], b0h, b1h);
                }
            }
        }
        __syncthreads();
    }

    // epilogue
    #pragma unroll
    for (int mi = 0; mi < 2; mi++) {
        #pragma unroll
        for (int half = 0; half < 2; half++) {
            int m = m0 + wm * 32 + mi * 16 + qr + half * 8;
            float* crow = C + (size_t)m * N;
            const float* rrow = res ? res + (size_t)m * N : nullptr;
            const float* prow = pos ? pos + (size_t)(m & (SEQ - 1)) * N : nullptr;
            #pragma unroll
            for (int ni = 0; ni < 8; ni++) {
                int n = n0 + wn * 64 + ni * 8 + 2 * qc;
                float v0 = acc[mi][ni][half * 2 + 0];
                float v1 = acc[mi][ni][half * 2 + 1];
                if (bias) { v0 += bias[n]; v1 += bias[n + 1]; }
                if (rrow) { v0 += rrow[n]; v1 += rrow[n + 1]; }
                if (prow) { v0 += prow[n]; v1 += prow[n + 1]; }
                if (act == 1) {
                    v0 = 0.5f * v0 * (1.0f + erff(v0 * 0.7071067811865475f));
                    v1 = 0.5f * v1 * (1.0f + erff(v1 * 0.7071067811865475f));
                }
                float2 o; o.x = v0; o.y = v1;
                *(float2*)(crow + n) = o;
            }
        }
    }
}

// ============================================================================
// LayerNorm over E=256. One warp per row.
// ============================================================================
__global__ __launch_bounds__(256)
void ln_kernel(const float* __restrict__ x, const float* __restrict__ g,
               const float* __restrict__ bt, float* __restrict__ y)
{
    int w = threadIdx.x >> 5, lane = threadIdx.x & 31;
    int row = blockIdx.x * 8 + w;
    const float* xr = x + (size_t)row * EMB;
    float4 v1 = *(const float4*)(xr + lane * 4);
    float4 v2 = *(const float4*)(xr + 128 + lane * 4);

    float s  = v1.x + v1.y + v1.z + v1.w + v2.x + v2.y + v2.z + v2.w;
    float ss = v1.x*v1.x + v1.y*v1.y + v1.z*v1.z + v1.w*v1.w
             + v2.x*v2.x + v2.y*v2.y + v2.z*v2.z + v2.w*v2.w;
    #pragma unroll
    for (int o = 16; o; o >>= 1) {
        s  += __shfl_xor_sync(0xFFFFFFFFu, s,  o);
        ss += __shfl_xor_sync(0xFFFFFFFFu, ss, o);
    }
    float mu  = s * (1.0f / EMB);
    float var = ss * (1.0f / EMB) - mu * mu;
    float rs  = rsqrtf(var + 1e-5f);

    float* yr = y + (size_t)row * EMB;
    int c = lane * 4;
    float4 o1, o2;
    o1.x = (v1.x - mu) * rs * g[c + 0] + bt[c + 0];
    o1.y = (v1.y - mu) * rs * g[c + 1] + bt[c + 1];
    o1.z = (v1.z - mu) * rs * g[c + 2] + bt[c + 2];
    o1.w = (v1.w - mu) * rs * g[c + 3] + bt[c + 3];
    o2.x = (v2.x - mu) * rs * g[c + 128] + bt[c + 128];
    o2.y = (v2.y - mu) * rs * g[c + 129] + bt[c + 129];
    o2.z = (v2.z - mu) * rs * g[c + 130] + bt[c + 130];
    o2.w = (v2.w - mu) * rs * g[c + 131] + bt[c + 131];
    *(float4*)(yr + c) = o1;
    *(float4*)(yr + 128 + c) = o2;
}

// ============================================================================
// Flash attention, fp32, online softmax. DH=32 in registers.
// ============================================================================
__global__ __launch_bounds__(128)
void attn_kernel(const float* __restrict__ qkv, float* __restrict__ ctx)
{
    __shared__ float Ks[64][32];
    __shared__ float Vs[64][32];

    int b = blockIdx.z, h = blockIdx.y;
    int tid = threadIdx.x;
    const float scale = 0.17677669529663687f;

    int qidx0 = blockIdx.x * 256 + tid;
    int qidx1 = qidx0 + 128;

    const float* qb = qkv + (size_t)b * SEQ * 768 + h * DHEAD;

    float q[2][32], acc[2][32];
    float mm[2] = { -1e30f, -1e30f };
    float ll[2] = { 0.f, 0.f };
    #pragma unroll
    for (int d4 = 0; d4 < 8; d4++) {
        float4 v0 = *(const float4*)(qb + (size_t)qidx0 * 768 + d4 * 4);
        float4 v1 = *(const float4*)(qb + (size_t)qidx1 * 768 + d4 * 4);
        q[0][d4*4+0] = v0.x; q[0][d4*4+1] = v0.y; q[0][d4*4+2] = v0.z; q[0][d4*4+3] = v0.w;
        q[1][d4*4+0] = v1.x; q[1][d4*4+1] = v1.y; q[1][d4*4+2] = v1.z; q[1][d4*4+3] = v1.w;
    }
    #pragma unroll
    for (int j = 0; j < 2; j++)
        #pragma unroll
        for (int d = 0; d < 32; d++) acc[j][d] = 0.f;

    for (int kc = 0; kc < SEQ; kc += 64) {
        #pragma unroll
        for (int i = 0; i < 4; i++) {
            int fidx = tid + i * 128;
            int key = fidx >> 3;
            int c = (fidx & 7) << 2;
            const float* src = qkv + (size_t)(b * SEQ + kc + key) * 768 + h * DHEAD;
            *(float4*)&Ks[key][c] = *(const float4*)(src + 256 + c);
            *(float4*)&Vs[key][c] = *(const float4*)(src + 512 + c);
        }
        __syncthreads();

        for (int kk = 0; kk < 64; kk++) {
            float s0 = 0.f, s1 = 0.f;
            #pragma unroll
            for (int d4 = 0; d4 < 8; d4++) {
                float4 kv = *(const float4*)&Ks[kk][d4 * 4];
                s0 += q[0][d4*4+0]*kv.x + q[0][d4*4+1]*kv.y + q[0][d4*4+2]*kv.z + q[0][d4*4+3]*kv.w;
                s1 += q[1][d4*4+0]*kv.x + q[1][d4*4+1]*kv.y + q[1][d4*4+2]*kv.z + q[1][d4*4+3]*kv.w;
            }
            s0 *= scale; s1 *= scale;

            float p0, p1;
            if (s0 > mm[0]) {
                float al = __expf(mm[0] - s0);
                ll[0] *= al;
                #pragma unroll
                for (int d = 0; d < 32; d++) acc[0][d] *= al;
                mm[0] = s0; p0 = 1.f;
            } else p0 = __expf(s0 - mm[0]);
            ll[0] += p0;
            if (s1 > mm[1]) {
                float al = __expf(mm[1] - s1);
                ll[1] *= al;
                #pragma unroll
                for (int d = 0; d < 32; d++) acc[1][d] *= al;
                mm[1] = s1; p1 = 1.f;
            } else p1 = __expf(s1 - mm[1]);
            ll[1] += p1;

            #pragma unroll
            for (int d4 = 0; d4 < 8; d4++) {
                float4 vv = *(const float4*)&Vs[kk][d4 * 4];
                acc[0][d4*4+0] += p0 * vv.x; acc[0][d4*4+1] += p0 * vv.y;
                acc[0][d4*4+2] += p0 * vv.z; acc[0][d4*4+3] += p0 * vv.w;
                acc[1][d4*4+0] += p1 * vv.x; acc[1][d4*4+1] += p1 * vv.y;
                acc[1][d4*4+2] += p1 * vv.z; acc[1][d4*4+3] += p1 * vv.w;
            }
        }
        __syncthreads();
    }

    float inv0 = 1.f / ll[0], inv1 = 1.f / ll[1];
    float* dst0 = ctx + (size_t)(b * SEQ + qidx0) * EMB + h * DHEAD;
    float* dst1 = ctx + (size_t)(b * SEQ + qidx1) * EMB + h * DHEAD;
    #pragma unroll
    for (int d4 = 0; d4 < 8; d4++) {
        float4 o0, o1;
        o0.x = acc[0][d4*4+0]*inv0; o0.y = acc[0][d4*4+1]*inv0;
        o0.z = acc[0][d4*4+2]*inv0; o0.w = acc[0][d4*4+3]*inv0;
        o1.x = acc[1][d4*4+0]*inv1; o1.y = acc[1][d4*4+1]*inv1;
        o1.z = acc[1][d4*4+2]*inv1; o1.w = acc[1][d4*4+3]*inv1;
        *(float4*)(dst0 + d4*4) = o0;
        *(float4*)(dst1 + d4*4) = o1;
    }
}

// ============================================================================
// Sequential RNN scan: packed f32x2 FMA over ALL 256 h elements
// (64 x ulonglong2 = 64 x 4 floats), double-buffered h, 1 barrier/step.
// ============================================================================
#define FMA2(d, a, b, c) asm("fma.rn.f32x2 %0, %1, %2, %3;" : "=l"(d) : "l"(a), "l"(b), "l"(c))

__global__ __launch_bounds__(256)
void scan_kernel(const float* __restrict__ xproj, const float* __restrict__ i2h_W,
                 const float* __restrict__ h0, float* __restrict__ hlast)
{
    __shared__ __align__(16) float hs[2][EMB];
    int b = blockIdx.x, e = threadIdx.x;
    hs[0][e] = h0[b * EMB + e];
    const ulonglong2* __restrict__ Wh = (const ulonglong2*)(i2h_W + (size_t)e * 512 + 256);
    const float* xp = xproj + (size_t)b * SEQ * EMB + e;
    __syncthreads();

    int p = 0;
    for (int t = 0; t < SEQ; t++) {
        const ulonglong2* h2 = (const ulonglong2*)hs[p];
        float x = xp[t * EMB];
        unsigned long long acc01, acc23;
        asm("mov.b64 %0, {%1, %2};" : "=l"(acc01) : "f"(x), "f"(0.0f));
        asm("mov.b64 %0, {%1, %2};" : "=l"(acc23) : "f"(0.0f), "f"(0.0f));
        #pragma unroll 16
        for (int k = 0; k < 64; k++) {     // 64 ulonglong2 = 256 floats (FIXED: was 16)
            ulonglong2 w = Wh[k];
            ulonglong2 hv = h2[k];
            FMA2(acc01, w.x, hv.x, acc01);
            FMA2(acc23, w.y, hv.y, acc23);
        }
        float a0, a1, a2, a3;
        asm("mov.b64 {%0, %1}, %2;" : "=f"(a0), "=f"(a1) : "l"(acc01));
        asm("mov.b64 {%0, %1}, %2;" : "=f"(a2), "=f"(a3) : "l"(acc23));
        float th = tanhf(a0 + a1 + a2 + a3);
        th = th > 0.f ? th : 0.f;
        p ^= 1;
        hs[p][e] = th;
        __syncthreads();
    }
    hlast[b * EMB + e] = hs[p][e];
}

// ============================================================================
// Final head
// ============================================================================
__global__ __launch_bounds__(256)
void final_kernel(const float* __restrict__ hlast, const float* __restrict__ h2o_W,
                  const float* __restrict__ h2o_b, const float* __restrict__ cls_W,
                  const float* __restrict__ cls_b, float* __restrict__ out)
{
    __shared__ float hs[EMB];
    __shared__ float red[EMB];
    int b = blockIdx.x, e = threadIdx.x;
    hs[e] = hlast[b * EMB + e];
    __syncthreads();

    float acc = h2o_b[e];
    const float4* wr = (const float4*)(h2o_W + (size_t)e * EMB);
    const float4* h4 = (const float4*)hs;
    #pragma unroll 16
    for (int k = 0; k < 64; k++) {
        float4 w = __ldg(&wr[k]);
        float4 hv = h4[k];
        acc += w.x*hv.x + w.y*hv.y + w.z*hv.z + w.w*hv.w;
    }
    out[OFF_SSM + b * EMB + e] = acc;
    red[e] = acc * cls_W[e];
    __syncthreads();
    #pragma unroll
    for (int o = 128; o; o >>= 1) {
        if (e < o) red[e] += red[e + o];
        __syncthreads();
    }
    if (e == 0) {
        float logit = red[0] + cls_b[0];
        out[b] = logit;
        out[OFF_PROBAS + b] = 1.f / (1.f + expf(-logit));
    }
}

// ============================================================================
__global__ __launch_bounds__(256)
void copy_kernel(const float* __restrict__ src, float* __restrict__ dst, int n4)
{
    int i = blockIdx.x * blockDim.x + threadIdx.x;
    if (i < n4) ((float4*)dst)[i] = ((const float4*)src)[i];
}

// ============================================================================
extern "C" void kernel_launch(void* const* d_in, const int* in_sizes, int n_in,
                              void* d_out, int out_size)
{
    const float* text_emb = (const float*)d_in[0];
    const float* pos     = (const float*)d_in[4];
    const float* text_W  = (const float*)d_in[5];
    const float* text_b  = (const float*)d_in[6];
    const float* ln1_g   = (const float*)d_in[9];
    const float* ln1_b   = (const float*)d_in[10];
    const float* qkv_W   = (const float*)d_in[11];
    const float* qkv_b   = (const float*)d_in[12];
    const float* out_W   = (const float*)d_in[13];
    const float* out_b   = (const float*)d_in[14];
    const float* ln2_g   = (const float*)d_in[15];
    const float* ln2_b   = (const float*)d_in[16];
    const float* ffn_W1  = (const float*)d_in[17];
    const float* ffn_b1  = (const float*)d_in[18];
    const float* ffn_W2  = (const float*)d_in[19];
    const float* ffn_b2  = (const float*)d_in[20];
    const float* cls_W   = (const float*)d_in[21];
    const float* cls_b   = (const float*)d_in[22];
    const float* i2h_W   = (const float*)d_in[23];
    const float* i2h_b   = (const float*)d_in[24];
    const float* h2o_W   = (const float*)d_in[25];
    const float* h2o_b   = (const float*)d_in[26];
    const float* h0      = (const float*)d_in[27];
    float* out = (float*)d_out;

    float *x, *ln, *qkv, *ctx, *ffn, *xproj, *hlast;
    cudaGetSymbolAddress((void**)&x,     g_x);
    cudaGetSymbolAddress((void**)&ln,    g_ln);
    cudaGetSymbolAddress((void**)&qkv,   g_qkv);
    cudaGetSymbolAddress((void**)&ctx,   g_ctx);
    cudaGetSymbolAddress((void**)&ffn,   g_ffn);
    cudaGetSymbolAddress((void**)&xproj, g_xproj);
    cudaGetSymbolAddress((void**)&hlast, g_hlast);

    const int SMEM_GEMM = 2 * STAGE_BYTES;   // 73728 B
    cudaFuncSetAttribute(gemm_tc, cudaFuncAttributeMaxDynamicSharedMemorySize, SMEM_GEMM);

    // 1) lang = text_emb @ text_W^T + text_b + pos_emb
    gemm_tc<<<dim3(2, 128), 256, SMEM_GEMM>>>(text_emb, text_W, 768, text_b, nullptr, pos,
                                              x, NTOK, EMB, 768, 0);

    // 2) two encoder layers (pre-LN)
    for (int l = 0; l < 2; l++) {
        ln_kernel<<<NTOK / 8, 256>>>(x, ln1_g + l * EMB, ln1_b + l * EMB, ln);
        gemm_tc<<<dim3(6, 128), 256, SMEM_GEMM>>>(ln, qkv_W + (size_t)l * 768 * EMB, EMB,
                                                  qkv_b + l * 768, nullptr, nullptr,
                                                  qkv, NTOK, 768, EMB, 0);
        attn_kernel<<<dim3(SEQ / 256, NHEAD, BATCH), 128>>>(qkv, ctx);
        gemm_tc<<<dim3(2, 128), 256, SMEM_GEMM>>>(ctx, out_W + (size_t)l * EMB * EMB, EMB,
                                                  out_b + l * EMB, x, nullptr,
                                                  x, NTOK, EMB, EMB, 0);
        ln_kernel<<<NTOK / 8, 256>>>(x, ln2_g + l * EMB, ln2_b + l * EMB, ln);
        gemm_tc<<<dim3(8, 128), 256, SMEM_GEMM>>>(ln, ffn_W1 + (size_t)l * 1024 * EMB, EMB,
                                                  ffn_b1 + l * 1024, nullptr, nullptr,
                                                  ffn, NTOK, 1024, EMB, 1);
        gemm_tc<<<dim3(2, 128), 256, SMEM_GEMM>>>(ffn, ffn_W2 + (size_t)l * EMB * 1024, 1024,
                                                  ffn_b2 + l * EMB, x, nullptr,
                                                  x, NTOK, EMB, 1024, 0);
    }

    // 3) final_vector -> output
    copy_kernel<<<(NTOK * EMB / 4 + 255) / 256, 256>>>(x, out + OFF_FINAL, NTOK * EMB / 4);

    // 4) xproj = x @ i2h_W[:, :256]^T + i2h_b  (row stride 512)
    gemm_tc<<<dim3(2, 128), 256, SMEM_GEMM>>>(x, i2h_W, 512, i2h_b, nullptr, nullptr,
                                              xproj, NTOK, EMB, EMB, 0);

    // 5) sequential scan
    scan_kernel<<<BATCH, 256>>>(xproj, i2h_W, h0, hlast);

    // 6) head
    final_kernel<<<BATCH, 256>>>(hlast, h2o_W, h2o_b, cls_W, cls_b, out);
}

// round 8
// speedup vs baseline: 1.0890x; 1.0585x over previous
#include <cuda_runtime.h>
#include <cstdint>
#include <math.h>

// Problem dims
#define BATCH 16
#define SEQ   1024
#define EMB   256
#define NTOK  16384   // BATCH*SEQ
#define NHEAD 8
#define DHEAD 32

// Output layout: logits[16] | probas[16] | final_vector[16*1024*256] | ssm[16*256]
#define OFF_PROBAS 16
#define OFF_FINAL  32
#define OFF_SSM    (32 + NTOK*EMB)

// -------- scratch (device globals; no allocations allowed) --------
__device__ float g_x[NTOK * EMB];
__device__ float g_ln[NTOK * EMB];
__device__ float g_qkv[NTOK * 3 * EMB];
__device__ float g_ctx[NTOK * EMB];
__device__ float g_ffn[NTOK * 4 * EMB];
__device__ float g_xproj[NTOK * EMB];
__device__ float g_hlast[BATCH * EMB];

// ================= PTX helpers =================
__device__ __forceinline__ uint32_t smem_u32(const void* p) {
    uint32_t a;
    asm("{ .reg .u64 t; cvta.to.shared.u64 t, %1; cvt.u32.u64 %0, t; }" : "=r"(a) : "l"(p));
    return a;
}
#define CP_ASYNC16(dst, src) \
    asm volatile("cp.async.cg.shared.global [%0], [%1], 16;" :: "r"(dst), "l"(src) : "memory")
#define CP_COMMIT() asm volatile("cp.async.commit_group;" ::: "memory")
#define CP_WAIT1()  asm volatile("cp.async.wait_group 1;" ::: "memory")
#define CP_WAIT0()  asm volatile("cp.async.wait_group 0;" ::: "memory")

__device__ __forceinline__ uint32_t f2tf32(float v) {
    uint32_t t;
    asm("cvt.rna.tf32.f32 %0, %1;" : "=r"(t) : "f"(v));
    return t;
}

__device__ __forceinline__ void mma_tf32(float* d,
                                         uint32_t a0, uint32_t a1, uint32_t a2, uint32_t a3,
                                         uint32_t b0, uint32_t b1) {
    asm volatile(
        "mma.sync.aligned.m16n8k8.row.col.f32.tf32.tf32.f32 "
        "{%0,%1,%2,%3}, {%4,%5,%6,%7}, {%8,%9}, {%0,%1,%2,%3};"
        : "+f"(d[0]), "+f"(d[1]), "+f"(d[2]), "+f"(d[3])
        : "r"(a0), "r"(a1), "r"(a2), "r"(a3), "r"(b0), "r"(b1));
}

// ============================================================================
// 1xTF32 mma.sync GEMM: C[M,N] = A[M,K] @ W[N,K]^T (+bias +res +pos, act)
// BM=BN=128, BK=32, 256 threads (4x2 warps, 32x64 warp tile).
// Smem rows padded to 36 floats (conflict-free fragment LDS).
// Single tf32 pass (rna rounding): measured logits error contribution ~1e-4.
// act: 0 none, 1 exact GELU. K % 32 == 0, M,N % 128 == 0.
// ============================================================================
#define PAD 36
#define STG_FLOATS (128 * PAD)            // per-operand stage: 4608 floats
#define STAGE_BYTES (2 * STG_FLOATS * 4)  // A+B: 36864 bytes

__global__ __launch_bounds__(256, 2)
void gemm_tc(const float* __restrict__ A, const float* __restrict__ W, int ldw,
             const float* __restrict__ bias, const float* __restrict__ res,
             const float* __restrict__ pos, float* __restrict__ C,
             int M, int N, int K, int act)
{
    extern __shared__ float smem[];   // [2 stages][A 128*36 | B 128*36]

    int tid = threadIdx.x;
    int wid = tid >> 5, lane = tid & 31;
    int wm = wid & 3;          // 0..3 -> 32 rows each
    int wn = wid >> 2;         // 0..1 -> 64 cols each
    int m0 = blockIdx.y * 128;
    int n0 = blockIdx.x * 128;

    uint32_t sbase = smem_u32(smem);

    // G->S load mapping: each thread loads 4 float4 of A and 4 of B per stage.
    int lrow = tid >> 1;               // 0..127
    int lc0  = (tid & 1) * 4;          // starting float4 chunk (0 or 4)
    const float* gA = A + (size_t)(m0 + lrow) * K;
    const float* gB = W + (size_t)(n0 + lrow) * ldw;
    uint32_t dstA = sbase + (uint32_t)(lrow * PAD * 4) + (uint32_t)(lc0 * 16);
    uint32_t dstB = dstA + (uint32_t)(STG_FLOATS * 4);

    float acc[2][8][4];
    #pragma unroll
    for (int i = 0; i < 2; i++)
        #pragma unroll
        for (int j = 0; j < 8; j++)
            #pragma unroll
            for (int r = 0; r < 4; r++) acc[i][j][r] = 0.f;

    int CCH = K >> 5;

    // prefetch chunk 0 -> stage 0
    #pragma unroll
    for (int j = 0; j < 4; j++) {
        CP_ASYNC16(dstA + j * 16u, gA + (lc0 + j) * 4);
        CP_ASYNC16(dstB + j * 16u, gB + (lc0 + j) * 4);
    }
    CP_COMMIT();

    // fragment base offsets (floats)
    int qr = lane >> 2;        // 0..7 (groupID)
    int qc = lane & 3;         // 0..3 (threadID_in_group)
    int aoff = (wm * 32 + qr) * PAD + qc;              // + mi*16*PAD + ks*8
    int boff = (wn * 64 + qr) * PAD + qc;              // + ni*8*PAD  + ks*8

    for (int c = 0; c < CCH; c++) {
        int st = c & 1;
        if (c + 1 < CCH) {
            int s2 = st ^ 1;
            uint32_t dA = dstA + (uint32_t)(s2 * STAGE_BYTES);
            uint32_t dB = dstB + (uint32_t)(s2 * STAGE_BYTES);
            const float* pA = gA + ((c + 1) << 5);
            const float* pB = gB + ((c + 1) << 5);
            #pragma unroll
            for (int j = 0; j < 4; j++) {
                CP_ASYNC16(dA + j * 16u, pA + (lc0 + j) * 4);
                CP_ASYNC16(dB + j * 16u, pB + (lc0 + j) * 4);
            }
            CP_COMMIT();
            CP_WAIT1();
        } else {
            CP_WAIT0();
        }
        __syncthreads();

        const float* As = smem + st * (2 * STG_FLOATS);
        const float* Bs = As + STG_FLOATS;

        #pragma unroll
        for (int ks = 0; ks < 4; ks++) {
            int kb = ks * 8;
            uint32_t af[2][4];
            #pragma unroll
            for (int mi = 0; mi < 2; mi++) {
                const float* ap = As + aoff + mi * 16 * PAD + kb;
                af[mi][0] = f2tf32(ap[0]);
                af[mi][1] = f2tf32(ap[8 * PAD]);
                af[mi][2] = f2tf32(ap[4]);
                af[mi][3] = f2tf32(ap[8 * PAD + 4]);
            }
            #pragma unroll
            for (int ni = 0; ni < 8; ni++) {
                const float* bp = Bs + boff + ni * 8 * PAD + kb;
                uint32_t b0 = f2tf32(bp[0]);
                uint32_t b1 = f2tf32(bp[4]);
                mma_tf32(acc[0][ni], af[0][0], af[0][1], af[0][2], af[0][3], b0, b1);
                mma_tf32(acc[1][ni], af[1][0], af[1][1], af[1][2], af[1][3], b0, b1);
            }
        }
        __syncthreads();
    }

    // epilogue
    #pragma unroll
    for (int mi = 0; mi < 2; mi++) {
        #pragma unroll
        for (int half = 0; half < 2; half++) {
            int m = m0 + wm * 32 + mi * 16 + qr + half * 8;
            float* crow = C + (size_t)m * N;
            const float* rrow = res ? res + (size_t)m * N : nullptr;
            const float* prow = pos ? pos + (size_t)(m & (SEQ - 1)) * N : nullptr;
            #pragma unroll
            for (int ni = 0; ni < 8; ni++) {
                int n = n0 + wn * 64 + ni * 8 + 2 * qc;
                float v0 = acc[mi][ni][half * 2 + 0];
                float v1 = acc[mi][ni][half * 2 + 1];
                if (bias) { v0 += bias[n]; v1 += bias[n + 1]; }
                if (rrow) { v0 += rrow[n]; v1 += rrow[n + 1]; }
                if (prow) { v0 += prow[n]; v1 += prow[n + 1]; }
                if (act == 1) {
                    v0 = 0.5f * v0 * (1.0f + erff(v0 * 0.7071067811865475f));
                    v1 = 0.5f * v1 * (1.0f + erff(v1 * 0.7071067811865475f));
                }
                float2 o; o.x = v0; o.y = v1;
                *(float2*)(crow + n) = o;
            }
        }
    }
}

// ============================================================================
// LayerNorm over E=256. One warp per row.
// ============================================================================
__global__ __launch_bounds__(256)
void ln_kernel(const float* __restrict__ x, const float* __restrict__ g,
               const float* __restrict__ bt, float* __restrict__ y)
{
    int w = threadIdx.x >> 5, lane = threadIdx.x & 31;
    int row = blockIdx.x * 8 + w;
    const float* xr = x + (size_t)row * EMB;
    float4 v1 = *(const float4*)(xr + lane * 4);
    float4 v2 = *(const float4*)(xr + 128 + lane * 4);

    float s  = v1.x + v1.y + v1.z + v1.w + v2.x + v2.y + v2.z + v2.w;
    float ss = v1.x*v1.x + v1.y*v1.y + v1.z*v1.z + v1.w*v1.w
             + v2.x*v2.x + v2.y*v2.y + v2.z*v2.z + v2.w*v2.w;
    #pragma unroll
    for (int o = 16; o; o >>= 1) {
        s  += __shfl_xor_sync(0xFFFFFFFFu, s,  o);
        ss += __shfl_xor_sync(0xFFFFFFFFu, ss, o);
    }
    float mu  = s * (1.0f / EMB);
    float var = ss * (1.0f / EMB) - mu * mu;
    float rs  = rsqrtf(var + 1e-5f);

    float* yr = y + (size_t)row * EMB;
    int c = lane * 4;
    float4 o1, o2;
    o1.x = (v1.x - mu) * rs * g[c + 0] + bt[c + 0];
    o1.y = (v1.y - mu) * rs * g[c + 1] + bt[c + 1];
    o1.z = (v1.z - mu) * rs * g[c + 2] + bt[c + 2];
    o1.w = (v1.w - mu) * rs * g[c + 3] + bt[c + 3];
    o2.x = (v2.x - mu) * rs * g[c + 128] + bt[c + 128];
    o2.y = (v2.y - mu) * rs * g[c + 129] + bt[c + 129];
    o2.z = (v2.z - mu) * rs * g[c + 130] + bt[c + 130];
    o2.w = (v2.w - mu) * rs * g[c + 131] + bt[c + 131];
    *(float4*)(yr + c) = o1;
    *(float4*)(yr + 128 + c) = o2;
}

// ============================================================================
// Flash attention, fp32, online softmax. DH=32 in registers.
// ============================================================================
__global__ __launch_bounds__(128)
void attn_kernel(const float* __restrict__ qkv, float* __restrict__ ctx)
{
    __shared__ float Ks[64][32];
    __shared__ float Vs[64][32];

    int b = blockIdx.z, h = blockIdx.y;
    int tid = threadIdx.x;
    const float scale = 0.17677669529663687f;

    int qidx0 = blockIdx.x * 256 + tid;
    int qidx1 = qidx0 + 128;

    const float* qb = qkv + (size_t)b * SEQ * 768 + h * DHEAD;

    float q[2][32], acc[2][32];
    float mm[2] = { -1e30f, -1e30f };
    float ll[2] = { 0.f, 0.f };
    #pragma unroll
    for (int d4 = 0; d4 < 8; d4++) {
        float4 v0 = *(const float4*)(qb + (size_t)qidx0 * 768 + d4 * 4);
        float4 v1 = *(const float4*)(qb + (size_t)qidx1 * 768 + d4 * 4);
        q[0][d4*4+0] = v0.x; q[0][d4*4+1] = v0.y; q[0][d4*4+2] = v0.z; q[0][d4*4+3] = v0.w;
        q[1][d4*4+0] = v1.x; q[1][d4*4+1] = v1.y; q[1][d4*4+2] = v1.z; q[1][d4*4+3] = v1.w;
    }
    #pragma unroll
    for (int j = 0; j < 2; j++)
        #pragma unroll
        for (int d = 0; d < 32; d++) acc[j][d] = 0.f;

    for (int kc = 0; kc < SEQ; kc += 64) {
        #pragma unroll
        for (int i = 0; i < 4; i++) {
            int fidx = tid + i * 128;
            int key = fidx >> 3;
            int c = (fidx & 7) << 2;
            const float* src = qkv + (size_t)(b * SEQ + kc + key) * 768 + h * DHEAD;
            *(float4*)&Ks[key][c] = *(const float4*)(src + 256 + c);
            *(float4*)&Vs[key][c] = *(const float4*)(src + 512 + c);
        }
        __syncthreads();

        for (int kk = 0; kk < 64; kk++) {
            float s0 = 0.f, s1 = 0.f;
            #pragma unroll
            for (int d4 = 0; d4 < 8; d4++) {
                float4 kv = *(const float4*)&Ks[kk][d4 * 4];
                s0 += q[0][d4*4+0]*kv.x + q[0][d4*4+1]*kv.y + q[0][d4*4+2]*kv.z + q[0][d4*4+3]*kv.w;
                s1 += q[1][d4*4+0]*kv.x + q[1][d4*4+1]*kv.y + q[1][d4*4+2]*kv.z + q[1][d4*4+3]*kv.w;
            }
            s0 *= scale; s1 *= scale;

            float p0, p1;
            if (s0 > mm[0]) {
                float al = __expf(mm[0] - s0);
                ll[0] *= al;
                #pragma unroll
                for (int d = 0; d < 32; d++) acc[0][d] *= al;
                mm[0] = s0; p0 = 1.f;
            } else p0 = __expf(s0 - mm[0]);
            ll[0] += p0;
            if (s1 > mm[1]) {
                float al = __expf(mm[1] - s1);
                ll[1] *= al;
                #pragma unroll
                for (int d = 0; d < 32; d++) acc[1][d] *= al;
                mm[1] = s1; p1 = 1.f;
            } else p1 = __expf(s1 - mm[1]);
            ll[1] += p1;

            #pragma unroll
            for (int d4 = 0; d4 < 8; d4++) {
                float4 vv = *(const float4*)&Vs[kk][d4 * 4];
                acc[0][d4*4+0] += p0 * vv.x; acc[0][d4*4+1] += p0 * vv.y;
                acc[0][d4*4+2] += p0 * vv.z; acc[0][d4*4+3] += p0 * vv.w;
                acc[1][d4*4+0] += p1 * vv.x; acc[1][d4*4+1] += p1 * vv.y;
                acc[1][d4*4+2] += p1 * vv.z; acc[1][d4*4+3] += p1 * vv.w;
            }
        }
        __syncthreads();
    }

    float inv0 = 1.f / ll[0], inv1 = 1.f / ll[1];
    float* dst0 = ctx + (size_t)(b * SEQ + qidx0) * EMB + h * DHEAD;
    float* dst1 = ctx + (size_t)(b * SEQ + qidx1) * EMB + h * DHEAD;
    #pragma unroll
    for (int d4 = 0; d4 < 8; d4++) {
        float4 o0, o1;
        o0.x = acc[0][d4*4+0]*inv0; o0.y = acc[0][d4*4+1]*inv0;
        o0.z = acc[0][d4*4+2]*inv0; o0.w = acc[0][d4*4+3]*inv0;
        o1.x = acc[1][d4*4+0]*inv1; o1.y = acc[1][d4*4+1]*inv1;
        o1.z = acc[1][d4*4+2]*inv1; o1.w = acc[1][d4*4+3]*inv1;
        *(float4*)(dst0 + d4*4) = o0;
        *(float4*)(dst1 + d4*4) = o1;
    }
}

// ============================================================================
// Sequential RNN scan: packed f32x2 FMA over all 256 h elements,
// 4 independent accumulation chains, double-buffered h, 1 barrier/step.
// ============================================================================
#define FMA2(d, a, b, c) asm("fma.rn.f32x2 %0, %1, %2, %3;" : "=l"(d) : "l"(a), "l"(b), "l"(c))

__global__ __launch_bounds__(256)
void scan_kernel(const float* __restrict__ xproj, const float* __restrict__ i2h_W,
                 const float* __restrict__ h0, float* __restrict__ hlast)
{
    __shared__ __align__(16) float hs[2][EMB];
    int b = blockIdx.x, e = threadIdx.x;
    hs[0][e] = h0[b * EMB + e];
    const ulonglong2* __restrict__ Wh = (const ulonglong2*)(i2h_W + (size_t)e * 512 + 256);
    const float* xp = xproj + (size_t)b * SEQ * EMB + e;
    __syncthreads();

    int p = 0;
    for (int t = 0; t < SEQ; t++) {
        const ulonglong2* h2 = (const ulonglong2*)hs[p];
        float x = xp[t * EMB];
        unsigned long long a0, a1, a2, a3;
        asm("mov.b64 %0, {%1, %2};" : "=l"(a0) : "f"(x), "f"(0.0f));
        asm("mov.b64 %0, {%1, %2};" : "=l"(a1) : "f"(0.0f), "f"(0.0f));
        a2 = a1; a3 = a1;
        #pragma unroll 8
        for (int k = 0; k < 64; k += 2) {      // 64 ulonglong2 = 256 floats
            ulonglong2 w  = Wh[k];
            ulonglong2 hv = h2[k];
            ulonglong2 w2  = Wh[k + 1];
            ulonglong2 hv2 = h2[k + 1];
            FMA2(a0, w.x,  hv.x,  a0);
            FMA2(a1, w.y,  hv.y,  a1);
            FMA2(a2, w2.x, hv2.x, a2);
            FMA2(a3, w2.y, hv2.y, a3);
        }
        float f0, f1, f2, f3, f4, f5, f6, f7;
        asm("mov.b64 {%0, %1}, %2;" : "=f"(f0), "=f"(f1) : "l"(a0));
        asm("mov.b64 {%0, %1}, %2;" : "=f"(f2), "=f"(f3) : "l"(a1));
        asm("mov.b64 {%0, %1}, %2;" : "=f"(f4), "=f"(f5) : "l"(a2));
        asm("mov.b64 {%0, %1}, %2;" : "=f"(f6), "=f"(f7) : "l"(a3));
        float th = tanhf(((f0 + f1) + (f2 + f3)) + ((f4 + f5) + (f6 + f7)));
        th = th > 0.f ? th : 0.f;
        p ^= 1;
        hs[p][e] = th;
        __syncthreads();
    }
    hlast[b * EMB + e] = hs[p][e];
}

// ============================================================================
// Final head
// ============================================================================
__global__ __launch_bounds__(256)
void final_kernel(const float* __restrict__ hlast, const float* __restrict__ h2o_W,
                  const float* __restrict__ h2o_b, const float* __restrict__ cls_W,
                  const float* __restrict__ cls_b, float* __restrict__ out)
{
    __shared__ float hs[EMB];
    __shared__ float red[EMB];
    int b = blockIdx.x, e = threadIdx.x;
    hs[e] = hlast[b * EMB + e];
    __syncthreads();

    float acc = h2o_b[e];
    const float4* wr = (const float4*)(h2o_W + (size_t)e * EMB);
    const float4* h4 = (const float4*)hs;
    #pragma unroll 16
    for (int k = 0; k < 64; k++) {
        float4 w = __ldg(&wr[k]);
        float4 hv = h4[k];
        acc += w.x*hv.x + w.y*hv.y + w.z*hv.z + w.w*hv.w;
    }
    out[OFF_SSM + b * EMB + e] = acc;
    red[e] = acc * cls_W[e];
    __syncthreads();
    #pragma unroll
    for (int o = 128; o; o >>= 1) {
        if (e < o) red[e] += red[e + o];
        __syncthreads();
    }
    if (e == 0) {
        float logit = red[0] + cls_b[0];
        out[b] = logit;
        out[OFF_PROBAS + b] = 1.f / (1.f + expf(-logit));
    }
}

// ============================================================================
__global__ __launch_bounds__(256)
void copy_kernel(const float* __restrict__ src, float* __restrict__ dst, int n4)
{
    int i = blockIdx.x * blockDim.x + threadIdx.x;
    if (i < n4) ((float4*)dst)[i] = ((const float4*)src)[i];
}

// ============================================================================
extern "C" void kernel_launch(void* const* d_in, const int* in_sizes, int n_in,
                              void* d_out, int out_size)
{
    const float* text_emb = (const float*)d_in[0];
    const float* pos     = (const float*)d_in[4];
    const float* text_W  = (const float*)d_in[5];
    const float* text_b  = (const float*)d_in[6];
    const float* ln1_g   = (const float*)d_in[9];
    const float* ln1_b   = (const float*)d_in[10];
    const float* qkv_W   = (const float*)d_in[11];
    const float* qkv_b   = (const float*)d_in[12];
    const float* out_W   = (const float*)d_in[13];
    const float* out_b   = (const float*)d_in[14];
    const float* ln2_g   = (const float*)d_in[15];
    const float* ln2_b   = (const float*)d_in[16];
    const float* ffn_W1  = (const float*)d_in[17];
    const float* ffn_b1  = (const float*)d_in[18];
    const float* ffn_W2  = (const float*)d_in[19];
    const float* ffn_b2  = (const float*)d_in[20];
    const float* cls_W   = (const float*)d_in[21];
    const float* cls_b   = (const float*)d_in[22];
    const float* i2h_W   = (const float*)d_in[23];
    const float* i2h_b   = (const float*)d_in[24];
    const float* h2o_W   = (const float*)d_in[25];
    const float* h2o_b   = (const float*)d_in[26];
    const float* h0      = (const float*)d_in[27];
    float* out = (float*)d_out;

    float *x, *ln, *qkv, *ctx, *ffn, *xproj, *hlast;
    cudaGetSymbolAddress((void**)&x,     g_x);
    cudaGetSymbolAddress((void**)&ln,    g_ln);
    cudaGetSymbolAddress((void**)&qkv,   g_qkv);
    cudaGetSymbolAddress((void**)&ctx,   g_ctx);
    cudaGetSymbolAddress((void**)&ffn,   g_ffn);
    cudaGetSymbolAddress((void**)&xproj, g_xproj);
    cudaGetSymbolAddress((void**)&hlast, g_hlast);

    const int SMEM_GEMM = 2 * STAGE_BYTES;   // 73728 B
    cudaFuncSetAttribute(gemm_tc, cudaFuncAttributeMaxDynamicSharedMemorySize, SMEM_GEMM);

    // 1) lang = text_emb @ text_W^T + text_b + pos_emb
    gemm_tc<<<dim3(2, 128), 256, SMEM_GEMM>>>(text_emb, text_W, 768, text_b, nullptr, pos,
                                              x, NTOK, EMB, 768, 0);

    // 2) two encoder layers (pre-LN)
    for (int l = 0; l < 2; l++) {
        ln_kernel<<<NTOK / 8, 256>>>(x, ln1_g + l * EMB, ln1_b + l * EMB, ln);
        gemm_tc<<<dim3(6, 128), 256, SMEM_GEMM>>>(ln, qkv_W + (size_t)l * 768 * EMB, EMB,
                                                  qkv_b + l * 768, nullptr, nullptr,
                                                  qkv, NTOK, 768, EMB, 0);
        attn_kernel<<<dim3(SEQ / 256, NHEAD, BATCH), 128>>>(qkv, ctx);
        gemm_tc<<<dim3(2, 128), 256, SMEM_GEMM>>>(ctx, out_W + (size_t)l * EMB * EMB, EMB,
                                                  out_b + l * EMB, x, nullptr,
                                                  x, NTOK, EMB, EMB, 0);
        ln_kernel<<<NTOK / 8, 256>>>(x, ln2_g + l * EMB, ln2_b + l * EMB, ln);
        gemm_tc<<<dim3(8, 128), 256, SMEM_GEMM>>>(ln, ffn_W1 + (size_t)l * 1024 * EMB, EMB,
                                                  ffn_b1 + l * 1024, nullptr, nullptr,
                                                  ffn, NTOK, 1024, EMB, 1);
        gemm_tc<<<dim3(2, 128), 256, SMEM_GEMM>>>(ffn, ffn_W2 + (size_t)l * EMB * 1024, 1024,
                                                  ffn_b2 + l * EMB, x, nullptr,
                                                  x, NTOK, EMB, 1024, 0);
    }

    // 3) final_vector -> output
    copy_kernel<<<(NTOK * EMB / 4 + 255) / 256, 256>>>(x, out + OFF_FINAL, NTOK * EMB / 4);

    // 4) xproj = x @ i2h_W[:, :256]^T + i2h_b  (row stride 512)
    gemm_tc<<<dim3(2, 128), 256, SMEM_GEMM>>>(x, i2h_W, 512, i2h_b, nullptr, nullptr,
                                              xproj, NTOK, EMB, EMB, 0);

    // 5) sequential scan
    scan_kernel<<<BATCH, 256>>>(xproj, i2h_W, h0, hlast);

    // 6) head
    final_kernel<<<BATCH, 256>>>(hlast, h2o_W, h2o_b, cls_W, cls_b, out);
}

// round 10
// speedup vs baseline: 4.3109x; 3.9585x over previous
#include <cuda_runtime.h>
#include <cstdint>
#include <math.h>

// Problem dims
#define BATCH 16
#define SEQ   1024
#define EMB   256
#define NTOK  16384   // BATCH*SEQ
#define NHEAD 8
#define DHEAD 32

// Output layout: logits[16] | probas[16] | final_vector[16*1024*256] | ssm[16*256]
#define OFF_PROBAS 16
#define OFF_FINAL  32
#define OFF_SSM    (32 + NTOK*EMB)

// -------- scratch (device globals; no allocations allowed) --------
__device__ float g_x[NTOK * EMB];
__device__ float g_ln[NTOK * EMB];
__device__ float g_qkv[NTOK * 3 * EMB];
__device__ float g_ctx[NTOK * EMB];
__device__ float g_ffn[NTOK * 4 * EMB];
__device__ float g_xproj[NTOK * EMB];
__device__ float g_hlast[BATCH * EMB];

// ================= PTX helpers =================
__device__ __forceinline__ uint32_t smem_u32(const void* p) {
    uint32_t a;
    asm("{ .reg .u64 t; cvta.to.shared.u64 t, %1; cvt.u32.u64 %0, t; }" : "=r"(a) : "l"(p));
    return a;
}
#define CP_ASYNC16(dst, src) \
    asm volatile("cp.async.cg.shared.global [%0], [%1], 16;" :: "r"(dst), "l"(src) : "memory")
#define CP_COMMIT() asm volatile("cp.async.commit_group;" ::: "memory")
#define CP_WAIT1()  asm volatile("cp.async.wait_group 1;" ::: "memory")
#define CP_WAIT0()  asm volatile("cp.async.wait_group 0;" ::: "memory")

__device__ __forceinline__ uint32_t f2tf32(float v) {
    uint32_t t;
    asm("cvt.rna.tf32.f32 %0, %1;" : "=r"(t) : "f"(v));
    return t;
}

__device__ __forceinline__ void mma_tf32(float* d,
                                         uint32_t a0, uint32_t a1, uint32_t a2, uint32_t a3,
                                         uint32_t b0, uint32_t b1) {
    asm volatile(
        "mma.sync.aligned.m16n8k8.row.col.f32.tf32.tf32.f32 "
        "{%0,%1,%2,%3}, {%4,%5,%6,%7}, {%8,%9}, {%0,%1,%2,%3};"
        : "+f"(d[0]), "+f"(d[1]), "+f"(d[2]), "+f"(d[3])
        : "r"(a0), "r"(a1), "r"(a2), "r"(a3), "r"(b0), "r"(b1));
}

// ============================================================================
// 1xTF32 mma.sync GEMM: C[M,N] = A[M,K] @ W[N,K]^T (+bias +res +pos, act)
// BM=BN=128, BK=32, 256 threads (4x2 warps, 32x64 warp tile).
// ============================================================================
#define PAD 36
#define STG_FLOATS (128 * PAD)            // per-operand stage: 4608 floats
#define STAGE_BYTES (2 * STG_FLOATS * 4)  // A+B: 36864 bytes

__global__ __launch_bounds__(256, 2)
void gemm_tc(const float* __restrict__ A, const float* __restrict__ W, int ldw,
             const float* __restrict__ bias, const float* __restrict__ res,
             const float* __restrict__ pos, float* __restrict__ C,
             int M, int N, int K, int act)
{
    extern __shared__ float smem[];   // [2 stages][A 128*36 | B 128*36]

    int tid = threadIdx.x;
    int wid = tid >> 5, lane = tid & 31;
    int wm = wid & 3;          // 0..3 -> 32 rows each
    int wn = wid >> 2;         // 0..1 -> 64 cols each
    int m0 = blockIdx.y * 128;
    int n0 = blockIdx.x * 128;

    uint32_t sbase = smem_u32(smem);

    int lrow = tid >> 1;               // 0..127
    int lc0  = (tid & 1) * 4;          // starting float4 chunk (0 or 4)
    const float* gA = A + (size_t)(m0 + lrow) * K;
    const float* gB = W + (size_t)(n0 + lrow) * ldw;
    uint32_t dstA = sbase + (uint32_t)(lrow * PAD * 4) + (uint32_t)(lc0 * 16);
    uint32_t dstB = dstA + (uint32_t)(STG_FLOATS * 4);

    float acc[2][8][4];
    #pragma unroll
    for (int i = 0; i < 2; i++)
        #pragma unroll
        for (int j = 0; j < 8; j++)
            #pragma unroll
            for (int r = 0; r < 4; r++) acc[i][j][r] = 0.f;

    int CCH = K >> 5;

    // prefetch chunk 0 -> stage 0
    #pragma unroll
    for (int j = 0; j < 4; j++) {
        CP_ASYNC16(dstA + j * 16u, gA + (lc0 + j) * 4);
        CP_ASYNC16(dstB + j * 16u, gB + (lc0 + j) * 4);
    }
    CP_COMMIT();

    int qr = lane >> 2;        // 0..7 (groupID)
    int qc = lane & 3;         // 0..3 (threadID_in_group)
    int aoff = (wm * 32 + qr) * PAD + qc;
    int boff = (wn * 64 + qr) * PAD + qc;

    for (int c = 0; c < CCH; c++) {
        int st = c & 1;
        if (c + 1 < CCH) {
            int s2 = st ^ 1;
            uint32_t dA = dstA + (uint32_t)(s2 * STAGE_BYTES);
            uint32_t dB = dstB + (uint32_t)(s2 * STAGE_BYTES);
            const float* pA = gA + ((c + 1) << 5);
            const float* pB = gB + ((c + 1) << 5);
            #pragma unroll
            for (int j = 0; j < 4; j++) {
                CP_ASYNC16(dA + j * 16u, pA + (lc0 + j) * 4);
                CP_ASYNC16(dB + j * 16u, pB + (lc0 + j) * 4);
            }
            CP_COMMIT();
            CP_WAIT1();
        } else {
            CP_WAIT0();
        }
        __syncthreads();

        const float* As = smem + st * (2 * STG_FLOATS);
        const float* Bs = As + STG_FLOATS;

        #pragma unroll
        for (int ks = 0; ks < 4; ks++) {
            int kb = ks * 8;
            uint32_t af[2][4];
            #pragma unroll
            for (int mi = 0; mi < 2; mi++) {
                const float* ap = As + aoff + mi * 16 * PAD + kb;
                af[mi][0] = f2tf32(ap[0]);
                af[mi][1] = f2tf32(ap[8 * PAD]);
                af[mi][2] = f2tf32(ap[4]);
                af[mi][3] = f2tf32(ap[8 * PAD + 4]);
            }
            #pragma unroll
            for (int ni = 0; ni < 8; ni++) {
                const float* bp = Bs + boff + ni * 8 * PAD + kb;
                uint32_t b0 = f2tf32(bp[0]);
                uint32_t b1 = f2tf32(bp[4]);
                mma_tf32(acc[0][ni], af[0][0], af[0][1], af[0][2], af[0][3], b0, b1);
                mma_tf32(acc[1][ni], af[1][0], af[1][1], af[1][2], af[1][3], b0, b1);
            }
        }
        __syncthreads();
    }

    // epilogue
    #pragma unroll
    for (int mi = 0; mi < 2; mi++) {
        #pragma unroll
        for (int half = 0; half < 2; half++) {
            int m = m0 + wm * 32 + mi * 16 + qr + half * 8;
            float* crow = C + (size_t)m * N;
            const float* rrow = res ? res + (size_t)m * N : nullptr;
            const float* prow = pos ? pos + (size_t)(m & (SEQ - 1)) * N : nullptr;
            #pragma unroll
            for (int ni = 0; ni < 8; ni++) {
                int n = n0 + wn * 64 + ni * 8 + 2 * qc;
                float v0 = acc[mi][ni][half * 2 + 0];
                float v1 = acc[mi][ni][half * 2 + 1];
                if (bias) { v0 += bias[n]; v1 += bias[n + 1]; }
                if (rrow) { v0 += rrow[n]; v1 += rrow[n + 1]; }
                if (prow) { v0 += prow[n]; v1 += prow[n + 1]; }
                if (act == 1) {
                    v0 = 0.5f * v0 * (1.0f + erff(v0 * 0.7071067811865475f));
                    v1 = 0.5f * v1 * (1.0f + erff(v1 * 0.7071067811865475f));
                }
                float2 o; o.x = v0; o.y = v1;
                *(float2*)(crow + n) = o;
            }
        }
    }
}

// ============================================================================
// LayerNorm over E=256. One warp per row.
// ============================================================================
__global__ __launch_bounds__(256)
void ln_kernel(const float* __restrict__ x, const float* __restrict__ g,
               const float* __restrict__ bt, float* __restrict__ y)
{
    int w = threadIdx.x >> 5, lane = threadIdx.x & 31;
    int row = blockIdx.x * 8 + w;
    const float* xr = x + (size_t)row * EMB;
    float4 v1 = *(const float4*)(xr + lane * 4);
    float4 v2 = *(const float4*)(xr + 128 + lane * 4);

    float s  = v1.x + v1.y + v1.z + v1.w + v2.x + v2.y + v2.z + v2.w;
    float ss = v1.x*v1.x + v1.y*v1.y + v1.z*v1.z + v1.w*v1.w
             + v2.x*v2.x + v2.y*v2.y + v2.z*v2.z + v2.w*v2.w;
    #pragma unroll
    for (int o = 16; o; o >>= 1) {
        s  += __shfl_xor_sync(0xFFFFFFFFu, s,  o);
        ss += __shfl_xor_sync(0xFFFFFFFFu, ss, o);
    }
    float mu  = s * (1.0f / EMB);
    float var = ss * (1.0f / EMB) - mu * mu;
    float rs  = rsqrtf(var + 1e-5f);

    float* yr = y + (size_t)row * EMB;
    int c = lane * 4;
    float4 o1, o2;
    o1.x = (v1.x - mu) * rs * g[c + 0] + bt[c + 0];
    o1.y = (v1.y - mu) * rs * g[c + 1] + bt[c + 1];
    o1.z = (v1.z - mu) * rs * g[c + 2] + bt[c + 2];
    o1.w = (v1.w - mu) * rs * g[c + 3] + bt[c + 3];
    o2.x = (v2.x - mu) * rs * g[c + 128] + bt[c + 128];
    o2.y = (v2.y - mu) * rs * g[c + 129] + bt[c + 129];
    o2.z = (v2.z - mu) * rs * g[c + 130] + bt[c + 130];
    o2.w = (v2.w - mu) * rs * g[c + 131] + bt[c + 131];
    *(float4*)(yr + c) = o1;
    *(float4*)(yr + 128 + c) = o2;
}

// ============================================================================
// Flash attention, fp32, online softmax. DH=32 in registers.
// ============================================================================
__global__ __launch_bounds__(128)
void attn_kernel(const float* __restrict__ qkv, float* __restrict__ ctx)
{
    __shared__ float Ks[64][32];
    __shared__ float Vs[64][32];

    int b = blockIdx.z, h = blockIdx.y;
    int tid = threadIdx.x;
    const float scale = 0.17677669529663687f;

    int qidx0 = blockIdx.x * 256 + tid;
    int qidx1 = qidx0 + 128;

    const float* qb = qkv + (size_t)b * SEQ * 768 + h * DHEAD;

    float q[2][32], acc[2][32];
    float mm[2] = { -1e30f, -1e30f };
    float ll[2] = { 0.f, 0.f };
    #pragma unroll
    for (int d4 = 0; d4 < 8; d4++) {
        float4 v0 = *(const float4*)(qb + (size_t)qidx0 * 768 + d4 * 4);
        float4 v1 = *(const float4*)(qb + (size_t)qidx1 * 768 + d4 * 4);
        q[0][d4*4+0] = v0.x; q[0][d4*4+1] = v0.y; q[0][d4*4+2] = v0.z; q[0][d4*4+3] = v0.w;
        q[1][d4*4+0] = v1.x; q[1][d4*4+1] = v1.y; q[1][d4*4+2] = v1.z; q[1][d4*4+3] = v1.w;
    }
    #pragma unroll
    for (int j = 0; j < 2; j++)
        #pragma unroll
        for (int d = 0; d < 32; d++) acc[j][d] = 0.f;

    for (int kc = 0; kc < SEQ; kc += 64) {
        #pragma unroll
        for (int i = 0; i < 4; i++) {
            int fidx = tid + i * 128;
            int key = fidx >> 3;
            int c = (fidx & 7) << 2;
            const float* src = qkv + (size_t)(b * SEQ + kc + key) * 768 + h * DHEAD;
            *(float4*)&Ks[key][c] = *(const float4*)(src + 256 + c);
            *(float4*)&Vs[key][c] = *(const float4*)(src + 512 + c);
        }
        __syncthreads();

        for (int kk = 0; kk < 64; kk++) {
            float s0 = 0.f, s1 = 0.f;
            #pragma unroll
            for (int d4 = 0; d4 < 8; d4++) {
                float4 kv = *(const float4*)&Ks[kk][d4 * 4];
                s0 += q[0][d4*4+0]*kv.x + q[0][d4*4+1]*kv.y + q[0][d4*4+2]*kv.z + q[0][d4*4+3]*kv.w;
                s1 += q[1][d4*4+0]*kv.x + q[1][d4*4+1]*kv.y + q[1][d4*4+2]*kv.z + q[1][d4*4+3]*kv.w;
            }
            s0 *= scale; s1 *= scale;

            float p0, p1;
            if (s0 > mm[0]) {
                float al = __expf(mm[0] - s0);
                ll[0] *= al;
                #pragma unroll
                for (int d = 0; d < 32; d++) acc[0][d] *= al;
                mm[0] = s0; p0 = 1.f;
            } else p0 = __expf(s0 - mm[0]);
            ll[0] += p0;
            if (s1 > mm[1]) {
                float al = __expf(mm[1] - s1);
                ll[1] *= al;
                #pragma unroll
                for (int d = 0; d < 32; d++) acc[1][d] *= al;
                mm[1] = s1; p1 = 1.f;
            } else p1 = __expf(s1 - mm[1]);
            ll[1] += p1;

            #pragma unroll
            for (int d4 = 0; d4 < 8; d4++) {
                float4 vv = *(const float4*)&Vs[kk][d4 * 4];
                acc[0][d4*4+0] += p0 * vv.x; acc[0][d4*4+1] += p0 * vv.y;
                acc[0][d4*4+2] += p0 * vv.z; acc[0][d4*4+3] += p0 * vv.w;
                acc[1][d4*4+0] += p1 * vv.x; acc[1][d4*4+1] += p1 * vv.y;
                acc[1][d4*4+2] += p1 * vv.z; acc[1][d4*4+3] += p1 * vv.w;
            }
        }
        __syncthreads();
    }

    float inv0 = 1.f / ll[0], inv1 = 1.f / ll[1];
    float* dst0 = ctx + (size_t)(b * SEQ + qidx0) * EMB + h * DHEAD;
    float* dst1 = ctx + (size_t)(b * SEQ + qidx1) * EMB + h * DHEAD;
    #pragma unroll
    for (int d4 = 0; d4 < 8; d4++) {
        float4 o0, o1;
        o0.x = acc[0][d4*4+0]*inv0; o0.y = acc[0][d4*4+1]*inv0;
        o0.z = acc[0][d4*4+2]*inv0; o0.w = acc[0][d4*4+3]*inv0;
        o1.x = acc[1][d4*4+0]*inv1; o1.y = acc[1][d4*4+1]*inv1;
        o1.z = acc[1][d4*4+2]*inv1; o1.w = acc[1][d4*4+3]*inv1;
        *(float4*)(dst0 + d4*4) = o0;
        *(float4*)(dst1 + d4*4) = o1;
    }
}

// ============================================================================
// Sequential RNN scan — cluster version.
// Grid = 32 (16 batches x 2 CTAs per cluster). Each CTA owns 128 rows of Wh,
// cached in REGISTERS (128 floats/thread, loaded once, coalesced) — no per-
// step weight traffic (the old version's 32-line-scattered LDGs were ~8 ms).
// Thread t: row = rank*128 + (t&127), col half = t>>7 (128 cols).
// h (full 256) double-buffered in SMEM; new h pushed to peer CTA via
// mapa + st.shared::cluster; one barrier.cluster per step.
// ============================================================================
#define FMA2(d, a, b, c) asm("fma.rn.f32x2 %0, %1, %2, %3;" : "=l"(d) : "l"(a), "l"(b), "l"(c))

__global__ __launch_bounds__(256) __cluster_dims__(2, 1, 1)
void scan_kernel(const float* __restrict__ xproj, const float* __restrict__ i2h_W,
                 const float* __restrict__ h0, float* __restrict__ hlast)
{
    __shared__ __align__(16) float hs[2][EMB];   // double-buffered full h
    __shared__ float part[256];

    uint32_t rank;
    asm("mov.u32 %0, %%cluster_ctarank;" : "=r"(rank));
    int b   = blockIdx.x >> 1;
    int tid = threadIdx.x;
    int lrow = tid & 127;
    int half = tid >> 7;
    int grow = (int)rank * 128 + lrow;           // global row this thread computes

    // Load this thread's 128 weight floats into registers (once).
    ulonglong2 w[32];
    {
        const ulonglong2* wp =
            (const ulonglong2*)(i2h_W + (size_t)grow * 512 + 256 + half * 128);
        #pragma unroll
        for (int i = 0; i < 32; i++) w[i] = wp[i];
    }

    // Both CTAs initialize their own full copy of h0 into buffer 0.
    hs[0][tid] = h0[b * EMB + tid];
    const float* xp = xproj + (size_t)b * SEQ * EMB + grow;
    __syncthreads();

    int p = 0;
    for (int t = 0; t < SEQ; t++) {
        float xv = 0.f;
        if (half == 0) xv = xp[t * EMB];         // prefetch early (hides L2 lat)

        const ulonglong2* h2 = (const ulonglong2*)(hs[p] + half * 128);
        unsigned long long a0, a1, a2, a3;
        asm("mov.b64 %0, {%1, %2};" : "=l"(a0) : "f"(0.0f), "f"(0.0f));
        a1 = a0; a2 = a0; a3 = a0;
        #pragma unroll
        for (int i = 0; i < 32; i += 2) {
            ulonglong2 hv  = h2[i];
            ulonglong2 hv2 = h2[i + 1];
            FMA2(a0, w[i].x,     hv.x,  a0);
            FMA2(a1, w[i].y,     hv.y,  a1);
            FMA2(a2, w[i + 1].x, hv2.x, a2);
            FMA2(a3, w[i + 1].y, hv2.y, a3);
        }
        float f0, f1, f2, f3, f4, f5, f6, f7;
        asm("mov.b64 {%0, %1}, %2;" : "=f"(f0), "=f"(f1) : "l"(a0));
        asm("mov.b64 {%0, %1}, %2;" : "=f"(f2), "=f"(f3) : "l"(a1));
        asm("mov.b64 {%0, %1}, %2;" : "=f"(f4), "=f"(f5) : "l"(a2));
        asm("mov.b64 {%0, %1}, %2;" : "=f"(f6), "=f"(f7) : "l"(a3));
        part[tid] = ((f0 + f1) + (f2 + f3)) + ((f4 + f5) + (f6 + f7));
        __syncthreads();

        int pn = p ^ 1;
        if (half == 0) {
            float v = tanhf(xv + part[lrow] + part[128 + lrow]);
            v = v > 0.f ? v : 0.f;
            hs[pn][grow] = v;                    // local copy
            uint32_t la = smem_u32(&hs[pn][grow]);
            uint32_t ra;
            asm("mapa.shared::cluster.u32 %0, %1, %2;"
                : "=r"(ra) : "r"(la), "r"(rank ^ 1u));
            asm volatile("st.shared::cluster.f32 [%0], %1;"
                         :: "r"(ra), "f"(v) : "memory");
        }
        p = pn;
        // Orders remote+local h writes before both CTAs' next-step reads,
        // and doubles as the block-wide barrier for the part[] buffer.
        asm volatile("barrier.cluster.arrive.aligned;" ::: "memory");
        asm volatile("barrier.cluster.wait.aligned;" ::: "memory");
    }
    if (half == 0) hlast[b * EMB + grow] = hs[p][grow];
}

// ============================================================================
// Final head
// ============================================================================
__global__ __launch_bounds__(256)
void final_kernel(const float* __restrict__ hlast, const float* __restrict__ h2o_W,
                  const float* __restrict__ h2o_b, const float* __restrict__ cls_W,
                  const float* __restrict__ cls_b, float* __restrict__ out)
{
    __shared__ float hs[EMB];
    __shared__ float red[EMB];
    int b = blockIdx.x, e = threadIdx.x;
    hs[e] = hlast[b * EMB + e];
    __syncthreads();

    float acc = h2o_b[e];
    const float4* wr = (const float4*)(h2o_W + (size_t)e * EMB);
    const float4* h4 = (const float4*)hs;
    #pragma unroll 16
    for (int k = 0; k < 64; k++) {
        float4 w = __ldg(&wr[k]);
        float4 hv = h4[k];
        acc += w.x*hv.x + w.y*hv.y + w.z*hv.z + w.w*hv.w;
    }
    out[OFF_SSM + b * EMB + e] = acc;
    red[e] = acc * cls_W[e];
    __syncthreads();
    #pragma unroll
    for (int o = 128; o; o >>= 1) {
        if (e < o) red[e] += red[e + o];
        __syncthreads();
    }
    if (e == 0) {
        float logit = red[0] + cls_b[0];
        out[b] = logit;
        out[OFF_PROBAS + b] = 1.f / (1.f + expf(-logit));
    }
}

// ============================================================================
__global__ __launch_bounds__(256)
void copy_kernel(const float* __restrict__ src, float* __restrict__ dst, int n4)
{
    int i = blockIdx.x * blockDim.x + threadIdx.x;
    if (i < n4) ((float4*)dst)[i] = ((const float4*)src)[i];
}

// ============================================================================
extern "C" void kernel_launch(void* const* d_in, const int* in_sizes, int n_in,
                              void* d_out, int out_size)
{
    const float* text_emb = (const float*)d_in[0];
    const float* pos     = (const float*)d_in[4];
    const float* text_W  = (const float*)d_in[5];
    const float* text_b  = (const float*)d_in[6];
    const float* ln1_g   = (const float*)d_in[9];
    const float* ln1_b   = (const float*)d_in[10];
    const float* qkv_W   = (const float*)d_in[11];
    const float* qkv_b   = (const float*)d_in[12];
    const float* out_W   = (const float*)d_in[13];
    const float* out_b   = (const float*)d_in[14];
    const float* ln2_g   = (const float*)d_in[15];
    const float* ln2_b   = (const float*)d_in[16];
    const float* ffn_W1  = (const float*)d_in[17];
    const float* ffn_b1  = (const float*)d_in[18];
    const float* ffn_W2  = (const float*)d_in[19];
    const float* ffn_b2  = (const float*)d_in[20];
    const float* cls_W   = (const float*)d_in[21];
    const float* cls_b   = (const float*)d_in[22];
    const float* i2h_W   = (const float*)d_in[23];
    const float* i2h_b   = (const float*)d_in[24];
    const float* h2o_W   = (const float*)d_in[25];
    const float* h2o_b   = (const float*)d_in[26];
    const float* h0      = (const float*)d_in[27];
    float* out = (float*)d_out;

    float *x, *ln, *qkv, *ctx, *ffn, *xproj, *hlast;
    cudaGetSymbolAddress((void**)&x,     g_x);
    cudaGetSymbolAddress((void**)&ln,    g_ln);
    cudaGetSymbolAddress((void**)&qkv,   g_qkv);
    cudaGetSymbolAddress((void**)&ctx,   g_ctx);
    cudaGetSymbolAddress((void**)&ffn,   g_ffn);
    cudaGetSymbolAddress((void**)&xproj, g_xproj);
    cudaGetSymbolAddress((void**)&hlast, g_hlast);

    const int SMEM_GEMM = 2 * STAGE_BYTES;   // 73728 B
    cudaFuncSetAttribute(gemm_tc, cudaFuncAttributeMaxDynamicSharedMemorySize, SMEM_GEMM);

    // 1) lang = text_emb @ text_W^T + text_b + pos_emb
    gemm_tc<<<dim3(2, 128), 256, SMEM_GEMM>>>(text_emb, text_W, 768, text_b, nullptr, pos,
                                              x, NTOK, EMB, 768, 0);

    // 2) two encoder layers (pre-LN)
    for (int l = 0; l < 2; l++) {
        ln_kernel<<<NTOK / 8, 256>>>(x, ln1_g + l * EMB, ln1_b + l * EMB, ln);
        gemm_tc<<<dim3(6, 128), 256, SMEM_GEMM>>>(ln, qkv_W + (size_t)l * 768 * EMB, EMB,
                                                  qkv_b + l * 768, nullptr, nullptr,
                                                  qkv, NTOK, 768, EMB, 0);
        attn_kernel<<<dim3(SEQ / 256, NHEAD, BATCH), 128>>>(qkv, ctx);
        gemm_tc<<<dim3(2, 128), 256, SMEM_GEMM>>>(ctx, out_W + (size_t)l * EMB * EMB, EMB,
                                                  out_b + l * EMB, x, nullptr,
                                                  x, NTOK, EMB, EMB, 0);
        ln_kernel<<<NTOK / 8, 256>>>(x, ln2_g + l * EMB, ln2_b + l * EMB, ln);
        gemm_tc<<<dim3(8, 128), 256, SMEM_GEMM>>>(ln, ffn_W1 + (size_t)l * 1024 * EMB, EMB,
                                                  ffn_b1 + l * 1024, nullptr, nullptr,
                                                  ffn, NTOK, 1024, EMB, 1);
        gemm_tc<<<dim3(2, 128), 256, SMEM_GEMM>>>(ffn, ffn_W2 + (size_t)l * EMB * 1024, 1024,
                                                  ffn_b2 + l * EMB, x, nullptr,
                                                  x, NTOK, EMB, 1024, 0);
    }

    // 3) final_vector -> output
    copy_kernel<<<(NTOK * EMB / 4 + 255) / 256, 256>>>(x, out + OFF_FINAL, NTOK * EMB / 4);

    // 4) xproj = x @ i2h_W[:, :256]^T + i2h_b  (row stride 512)
    gemm_tc<<<dim3(2, 128), 256, SMEM_GEMM>>>(x, i2h_W, 512, i2h_b, nullptr, nullptr,
                                              xproj, NTOK, EMB, EMB, 0);

    // 5) sequential scan (cluster of 2 CTAs per batch, weights in registers)
    scan_kernel<<<BATCH * 2, 256>>>(xproj, i2h_W, h0, hlast);

    // 6) head
    final_kernel<<<BATCH, 256>>>(hlast, h2o_W, h2o_b, cls_W, cls_b, out);
}